// round 2
// baseline (speedup 1.0000x reference)
#include <cuda_runtime.h>
#include <cuda_fp16.h>
#include <stdint.h>

#define DB    512   // batch
#define DN    512   // steps
#define DNX   512
#define DNU   256
#define DNY   256
#define DNW   256
#define DK1   768   // nx+nu
#define DK2   1024  // nx+nu+nw
#define NBLK  128
#define NTHR  128

// ---------------- device scratch (no allocs allowed -> __device__ globals) ---------
__device__ __half g_ush[(size_t)DB * DN * DNU];
__device__ __half g_usl[(size_t)DB * DN * DNU];
__device__ __half g_W1h[DNW * DK1];
__device__ __half g_W1l[DNW * DK1];
__device__ __half g_W2h[(DNX + DNY) * DK2];
__device__ __half g_W2l[(DNX + DNY) * DK2];
__device__ __half g_xh[2 * DB * DNX];
__device__ __half g_xl[2 * DB * DNX];
__device__ __half g_wh[2 * DB * DNW];
__device__ __half g_wl[2 * DB * DNW];
__device__ unsigned g_bar_count;   // zero-init, self-resetting
__device__ unsigned g_bar_phase;   // monotonic across replays (equality-checked)

// ---------------- small helpers ----------------
__device__ __forceinline__ void splitf(float v, __half& h, __half& l) {
    h = __float2half_rn(v);
    l = __float2half_rn(v - __half2float(h));
}

__device__ __forceinline__ unsigned sptr(const void* p) {
    return (unsigned)__cvta_generic_to_shared(p);
}

__device__ __forceinline__ void ldsm_x4(unsigned* r, unsigned a) {
    asm volatile("ldmatrix.sync.aligned.m8n8.x4.shared.b16 {%0,%1,%2,%3}, [%4];"
                 : "=r"(r[0]), "=r"(r[1]), "=r"(r[2]), "=r"(r[3]) : "r"(a));
}

__device__ __forceinline__ void mma16816(float* c, const unsigned* a, const unsigned* b) {
    asm volatile(
        "mma.sync.aligned.m16n8k16.row.col.f32.f16.f16.f32 "
        "{%0,%1,%2,%3}, {%4,%5,%6,%7}, {%8,%9}, {%0,%1,%2,%3};\n"
        : "+f"(c[0]), "+f"(c[1]), "+f"(c[2]), "+f"(c[3])
        : "r"(a[0]), "r"(a[1]), "r"(a[2]), "r"(a[3]), "r"(b[0]), "r"(b[1]));
}

// grid barrier: all NBLK CTAs co-resident (NBLK <= 148 SMs) so spinning is safe
__device__ __forceinline__ void grid_bar(unsigned target) {
    __syncthreads();
    if (threadIdx.x == 0) {
        __threadfence();
        unsigned a = atomicAdd(&g_bar_count, 1u);
        if (a == NBLK - 1u) {
            g_bar_count = 0u;
            __threadfence();
            atomicExch(&g_bar_phase, target);
        } else {
            unsigned v;
            do { __nanosleep(64); v = *(volatile unsigned*)&g_bar_phase; } while (v != target);
        }
        __threadfence();
    }
    __syncthreads();
}

// ---------------- prep kernels ----------------
__global__ void prep_weights(const float* __restrict__ A,  const float* __restrict__ B1,
                             const float* __restrict__ B2, const float* __restrict__ C1,
                             const float* __restrict__ D11, const float* __restrict__ D12,
                             const float* __restrict__ C2, const float* __restrict__ D21,
                             const float* __restrict__ x0) {
    const int SZ1 = DNW * DK1;
    const int SZ2 = (DNX + DNY) * DK2;
    const int SZX = DB * DNX;
    const int tot = SZ1 + SZ2 + SZX;
    for (int i = blockIdx.x * blockDim.x + threadIdx.x; i < tot;
         i += gridDim.x * blockDim.x) {
        float v; __half h, l;
        if (i < SZ1) {
            int n = i / DK1, k = i % DK1;
            v = (k < DNX) ? C2[n * DNX + k] : D21[n * DNU + (k - DNX)];
            splitf(v, h, l); g_W1h[i] = h; g_W1l[i] = l;
        } else if (i < SZ1 + SZ2) {
            int j = i - SZ1;
            int n = j / DK2, k = j % DK2;
            if (n < DNX) {
                v = (k < DNX) ? A[n * DNX + k]
                  : (k < DNX + DNU) ? B1[n * DNU + (k - DNX)]
                  : B2[n * DNW + (k - DNX - DNU)];
            } else {
                int r = n - DNX;
                v = (k < DNX) ? C1[r * DNX + k]
                  : (k < DNX + DNU) ? D11[r * DNU + (k - DNX)]
                  : D12[r * DNW + (k - DNX - DNU)];
            }
            splitf(v, h, l); g_W2h[j] = h; g_W2l[j] = l;
        } else {
            int j = i - SZ1 - SZ2;
            v = x0[j];
            splitf(v, h, l); g_xh[j] = h; g_xl[j] = l;   // x_0 -> buffer 0
        }
    }
}

__global__ void prep_us(const float* __restrict__ us) {
    size_t n = (size_t)DB * DN * DNU;
    for (size_t i = blockIdx.x * (size_t)blockDim.x + threadIdx.x; i < n;
         i += (size_t)gridDim.x * blockDim.x) {
        float v = us[i]; __half h, l; splitf(v, h, l);
        g_ush[i] = h; g_usl[i] = l;
    }
}

// ---------------- A-operand source (piecewise [x | u_s | w]) ----------------
__device__ __forceinline__ void a_ptrs(int m, int k0, int s,
                                       const __half* xh, const __half* xl,
                                       const __half* wh, const __half* wl,
                                       const __half** ph, const __half** pl) {
    if (k0 < DNX) {
        size_t o = (size_t)m * DNX + k0; *ph = xh + o; *pl = xl + o;
    } else if (k0 < DNX + DNU) {
        size_t o = ((size_t)m * DN + s) * DNU + (k0 - DNX);
        *ph = g_ush + o; *pl = g_usl + o;
    } else {
        size_t o = (size_t)m * DNW + (k0 - DNX - DNU);
        *ph = wh + o; *pl = wl + o;
    }
}

// ---------------- generic 32x64 output tile, K-loop in 64-chunks ----------------
// mode 0: tanh -> w buffer (parity s&1)        [P1]
// mode 1: split -> x buffer (parity (s+1)&1)   [P2x]
// mode 2: f32 -> out[b][s][col]                [P2y]
__device__ void tile_run(float* __restrict__ out,
                         int M0, int N0, int wn0, int Klen, int s,
                         int xpar, int wpar, int mode,
                         const __half* __restrict__ Wh,
                         const __half* __restrict__ Wl, int ldw) {
    __shared__ __half sAh[32][72], sAl[32][72];
    __shared__ __half sBh[64][72], sBl[64][72];

    const int tid = threadIdx.x;
    const int lane = tid & 31, wid = tid >> 5;
    const int wm = wid & 1, wn = wid >> 1;

    const __half* xh = g_xh + (size_t)xpar * DB * DNX;
    const __half* xl = g_xl + (size_t)xpar * DB * DNX;
    const __half* wbh = g_wh + (size_t)wpar * DB * DNW;
    const __half* wbl = g_wl + (size_t)wpar * DB * DNW;

    float acc[16];
#pragma unroll
    for (int i = 0; i < 16; ++i) acc[i] = 0.f;

    for (int kc = 0; kc < Klen; kc += 64) {
        __syncthreads();
        // A: 32 rows x 64 halves (hi & lo) -> 2 uint4 per thread per buffer
#pragma unroll
        for (int t = 0; t < 2; ++t) {
            int j = tid + t * NTHR;
            int r = j >> 3, c = j & 7;
            const __half *ph, *pl;
            a_ptrs(M0 + r, kc, s, xh, xl, wbh, wbl, &ph, &pl);
            *reinterpret_cast<uint4*>(&sAh[r][c * 8]) =
                __ldcg(reinterpret_cast<const uint4*>(ph + c * 8));
            *reinterpret_cast<uint4*>(&sAl[r][c * 8]) =
                __ldcg(reinterpret_cast<const uint4*>(pl + c * 8));
        }
        // B: 64 rows x 64 halves (hi & lo), weights are constant -> cached loads
#pragma unroll
        for (int t = 0; t < 4; ++t) {
            int j = tid + t * NTHR;
            int r = j >> 3, c = j & 7;
            size_t o = (size_t)(wn0 + r) * ldw + kc + c * 8;
            *reinterpret_cast<uint4*>(&sBh[r][c * 8]) =
                *reinterpret_cast<const uint4*>(Wh + o);
            *reinterpret_cast<uint4*>(&sBl[r][c * 8]) =
                *reinterpret_cast<const uint4*>(Wl + o);
        }
        __syncthreads();

#pragma unroll
        for (int kk = 0; kk < 4; ++kk) {
            unsigned ah[4], al[4], bh[8], bl[8];
            int ar = wm * 16 + (lane & 15);
            int ac = kk * 16 + ((lane >> 4) << 3);
            ldsm_x4(ah, sptr(&sAh[ar][ac]));
            ldsm_x4(al, sptr(&sAl[ar][ac]));
            int br = wn * 32 + ((lane >> 4) << 3) + (lane & 7);
            int bc = kk * 16 + (((lane >> 3) & 1) << 3);
            ldsm_x4(bh,     sptr(&sBh[br][bc]));
            ldsm_x4(bh + 4, sptr(&sBh[br + 16][bc]));
            ldsm_x4(bl,     sptr(&sBl[br][bc]));
            ldsm_x4(bl + 4, sptr(&sBl[br + 16][bc]));
#pragma unroll
            for (int nf = 0; nf < 4; ++nf) {
                mma16816(acc + 4 * nf, ah, bh + 2 * nf);
                mma16816(acc + 4 * nf, al, bh + 2 * nf);
                mma16816(acc + 4 * nf, ah, bl + 2 * nf);
            }
        }
    }

    // ---- epilogue ----
    const int r0 = M0 + wm * 16 + (lane >> 2);
    const int c0 = N0 + wn * 32 + (lane & 3) * 2;

    if (mode == 0) {
        __half* Dh = g_wh + (size_t)(s & 1) * DB * DNW;
        __half* Dl = g_wl + (size_t)(s & 1) * DB * DNW;
#pragma unroll
        for (int nf = 0; nf < 4; ++nf) {
#pragma unroll
            for (int rh = 0; rh < 2; ++rh) {
                int row = r0 + rh * 8, col = c0 + nf * 8;
                float v0 = tanhf(acc[nf * 4 + rh * 2 + 0]);
                float v1 = tanhf(acc[nf * 4 + rh * 2 + 1]);
                __half h0, l0, h1, l1; splitf(v0, h0, l0); splitf(v1, h1, l1);
                size_t o = (size_t)row * DNW + col;
                *reinterpret_cast<__half2*>(&Dh[o]) = __halves2half2(h0, h1);
                *reinterpret_cast<__half2*>(&Dl[o]) = __halves2half2(l0, l1);
            }
        }
    } else if (mode == 1) {
        __half* Dh = g_xh + (size_t)((s + 1) & 1) * DB * DNX;
        __half* Dl = g_xl + (size_t)((s + 1) & 1) * DB * DNX;
#pragma unroll
        for (int nf = 0; nf < 4; ++nf) {
#pragma unroll
            for (int rh = 0; rh < 2; ++rh) {
                int row = r0 + rh * 8, col = c0 + nf * 8;
                float v0 = acc[nf * 4 + rh * 2 + 0];
                float v1 = acc[nf * 4 + rh * 2 + 1];
                __half h0, l0, h1, l1; splitf(v0, h0, l0); splitf(v1, h1, l1);
                size_t o = (size_t)row * DNX + col;
                *reinterpret_cast<__half2*>(&Dh[o]) = __halves2half2(h0, h1);
                *reinterpret_cast<__half2*>(&Dl[o]) = __halves2half2(l0, l1);
            }
        }
    } else {
#pragma unroll
        for (int nf = 0; nf < 4; ++nf) {
#pragma unroll
            for (int rh = 0; rh < 2; ++rh) {
                int row = r0 + rh * 8, col = c0 + nf * 8;
                float2 v = make_float2(acc[nf * 4 + rh * 2 + 0],
                                       acc[nf * 4 + rh * 2 + 1]);
                *reinterpret_cast<float2*>(
                    &out[((size_t)row * DN + s) * DNY + col]) = v;
            }
        }
    }
}

// ---------------- persistent main kernel ----------------
__global__ void __launch_bounds__(NTHR, 1) lure_main(float* __restrict__ out) {
    const int bid = blockIdx.x;
    __shared__ unsigned s_base;
    if (threadIdx.x == 0) s_base = atomicAdd(&g_bar_phase, 0u);
    __syncthreads();
    unsigned nbar = 0;

    const int M0 = (bid & 15) * 32;

    for (int k = 0; k <= DN; ++k) {
        // phase alpha: CTAs 0-63: P1(k) (w_k); CTAs 64-127: P2y(k-1) (y_{k-1})
        if (bid < 64) {
            if (k < DN) {
                int N0 = (bid >> 4) * 64;
                tile_run(out, M0, N0, N0, DK1, k, k & 1, 0, 0, g_W1h, g_W1l, DK1);
            }
        } else {
            if (k >= 1) {
                int b2 = bid - 64;
                int N0 = (b2 >> 4) * 64;
                tile_run(out, M0, N0, DNX + N0, DK2, k - 1,
                         (k - 1) & 1, (k - 1) & 1, 2, g_W2h, g_W2l, DK2);
            }
        }
        grid_bar(s_base + (++nbar));
        // phase beta: all 128 CTAs: P2x(k) (x_{k+1})
        if (k < DN) {
            int N0 = (bid >> 4) * 64;
            tile_run(out, M0, N0, N0, DK2, k, k & 1, k & 1, 1, g_W2h, g_W2l, DK2);
            grid_bar(s_base + (++nbar));
        }
    }
}

// ---------------- launch ----------------
extern "C" void kernel_launch(void* const* d_in, const int* in_sizes, int n_in,
                              void* d_out, int out_size) {
    const float* x0  = (const float*)d_in[0];
    const float* us  = (const float*)d_in[1];
    const float* A   = (const float*)d_in[2];
    const float* B1  = (const float*)d_in[3];
    const float* B2  = (const float*)d_in[4];
    const float* C1  = (const float*)d_in[5];
    const float* D11 = (const float*)d_in[6];
    const float* D12 = (const float*)d_in[7];
    const float* C2  = (const float*)d_in[8];
    const float* D21 = (const float*)d_in[9];

    prep_weights<<<512, 256>>>(A, B1, B2, C1, D11, D12, C2, D21, x0);
    prep_us<<<8192, 256>>>(us);
    lure_main<<<NBLK, NTHR>>>((float*)d_out);
}

// round 3
// speedup vs baseline: 1.5197x; 1.5197x over previous
#include <cuda_runtime.h>
#include <cuda_fp16.h>
#include <stdint.h>

#define DB    512   // batch
#define DN    512   // steps
#define DNX   512
#define DNU   256
#define DNY   256
#define DNW   256
#define DK1   768   // nx+nu
#define DK2   1024  // nx+nu+nw
#define NBLK  128
#define NTHR  256
#define SSTR  72    // 64 halves + 8 pad (144B rows, 16B aligned, ldsm conflict-free)

// ---------------- device scratch (no allocs allowed -> __device__ globals) ---------
__device__ __half g_ush[(size_t)DB * DN * DNU];
__device__ __half g_usl[(size_t)DB * DN * DNU];
__device__ __half g_W1h[DNW * DK1];
__device__ __half g_W1l[DNW * DK1];
__device__ __half g_W2h[(DNX + DNY) * DK2];
__device__ __half g_W2l[(DNX + DNY) * DK2];
__device__ __half g_xh[2 * DB * DNX];
__device__ __half g_xl[2 * DB * DNX];
__device__ __half g_wh[2 * DB * DNW];
__device__ __half g_wl[2 * DB * DNW];
__device__ unsigned g_bar_count;   // zero-init, self-resetting
__device__ unsigned g_bar_phase;   // monotonic across replays (equality-checked)

// ---------------- smem layout: 3-stage pipeline ----------------
struct Smem {
    __half Ah[3][32][SSTR];
    __half Al[3][32][SSTR];
    __half Bh[3][64][SSTR];
    __half Bl[3][64][SSTR];
};

// ---------------- small helpers ----------------
__device__ __forceinline__ void splitf(float v, __half& h, __half& l) {
    h = __float2half_rn(v);
    l = __float2half_rn(v - __half2float(h));
}

__device__ __forceinline__ unsigned sptr(const void* p) {
    return (unsigned)__cvta_generic_to_shared(p);
}

__device__ __forceinline__ void ldsm_x4(unsigned* r, unsigned a) {
    asm volatile("ldmatrix.sync.aligned.m8n8.x4.shared.b16 {%0,%1,%2,%3}, [%4];"
                 : "=r"(r[0]), "=r"(r[1]), "=r"(r[2]), "=r"(r[3]) : "r"(a));
}

__device__ __forceinline__ void mma16816(float* c, const unsigned* a, const unsigned* b) {
    asm volatile(
        "mma.sync.aligned.m16n8k16.row.col.f32.f16.f16.f32 "
        "{%0,%1,%2,%3}, {%4,%5,%6,%7}, {%8,%9}, {%0,%1,%2,%3};\n"
        : "+f"(c[0]), "+f"(c[1]), "+f"(c[2]), "+f"(c[3])
        : "r"(a[0]), "r"(a[1]), "r"(a[2]), "r"(a[3]), "r"(b[0]), "r"(b[1]));
}

__device__ __forceinline__ void cpasync16(unsigned s, const void* g) {
    asm volatile("cp.async.cg.shared.global [%0], [%1], 16;" :: "r"(s), "l"(g));
}
__device__ __forceinline__ void cp_commit() {
    asm volatile("cp.async.commit_group;");
}

// grid barrier: all NBLK CTAs co-resident (NBLK <= 148 SMs) so spinning is safe
__device__ __forceinline__ void grid_bar(unsigned target) {
    __threadfence();                 // release: every thread's stores visible GPU-wide
    __syncthreads();
    if (threadIdx.x == 0) {
        unsigned a = atomicAdd(&g_bar_count, 1u);
        if (a == NBLK - 1u) {
            g_bar_count = 0u;
            __threadfence();
            atomicExch(&g_bar_phase, target);
        } else {
            unsigned v;
            do { __nanosleep(64); v = *(volatile unsigned*)&g_bar_phase; } while (v != target);
        }
        __threadfence();
    }
    __syncthreads();
}

// ---------------- prep kernels ----------------
__global__ void prep_weights(const float* __restrict__ A,  const float* __restrict__ B1,
                             const float* __restrict__ B2, const float* __restrict__ C1,
                             const float* __restrict__ D11, const float* __restrict__ D12,
                             const float* __restrict__ C2, const float* __restrict__ D21,
                             const float* __restrict__ x0) {
    const int SZ1 = DNW * DK1;
    const int SZ2 = (DNX + DNY) * DK2;
    const int SZX = DB * DNX;
    const int tot = SZ1 + SZ2 + SZX;
    for (int i = blockIdx.x * blockDim.x + threadIdx.x; i < tot;
         i += gridDim.x * blockDim.x) {
        float v; __half h, l;
        if (i < SZ1) {
            int n = i / DK1, k = i % DK1;
            v = (k < DNX) ? C2[n * DNX + k] : D21[n * DNU + (k - DNX)];
            splitf(v, h, l); g_W1h[i] = h; g_W1l[i] = l;
        } else if (i < SZ1 + SZ2) {
            int j = i - SZ1;
            int n = j / DK2, k = j % DK2;
            if (n < DNX) {
                v = (k < DNX) ? A[n * DNX + k]
                  : (k < DNX + DNU) ? B1[n * DNU + (k - DNX)]
                  : B2[n * DNW + (k - DNX - DNU)];
            } else {
                int r = n - DNX;
                v = (k < DNX) ? C1[r * DNX + k]
                  : (k < DNX + DNU) ? D11[r * DNU + (k - DNX)]
                  : D12[r * DNW + (k - DNX - DNU)];
            }
            splitf(v, h, l); g_W2h[j] = h; g_W2l[j] = l;
        } else {
            int j = i - SZ1 - SZ2;
            v = x0[j];
            splitf(v, h, l); g_xh[j] = h; g_xl[j] = l;   // x_0 -> buffer 0
        }
    }
}

__global__ void prep_us(const float* __restrict__ us) {
    size_t n2 = (size_t)DB * DN * DNU / 2;
    const float2* us2 = (const float2*)us;
    __half2* uh2 = (__half2*)g_ush;
    __half2* ul2 = (__half2*)g_usl;
    for (size_t i = blockIdx.x * (size_t)blockDim.x + threadIdx.x; i < n2;
         i += (size_t)gridDim.x * blockDim.x) {
        float2 v = us2[i];
        __half h0, l0, h1, l1; splitf(v.x, h0, l0); splitf(v.y, h1, l1);
        uh2[i] = __halves2half2(h0, h1);
        ul2[i] = __halves2half2(l0, l1);
    }
}

// ---------------- chunk loader (cp.async) ----------------
__device__ __forceinline__ void load_chunk(Smem* sm, int buf, int M0, int wn0,
                                           int kc, int s,
                                           const __half* xh, const __half* xl,
                                           const __half* wbh, const __half* wbl,
                                           const __half* Wh, const __half* Wl, int ldw) {
    const int tid = threadIdx.x;
    // A: 32 rows x 64 halves, hi & lo (one 16B op each per thread)
    {
        int r = tid >> 3, co = (tid & 7) * 8;
        int m = M0 + r;
        const __half *ph, *pl;
        if (kc < DNX)            { size_t o = (size_t)m * DNX + kc;                      ph = xh + o;   pl = xl + o; }
        else if (kc < DNX + DNU) { size_t o = ((size_t)m * DN + s) * DNU + (kc - DNX);   ph = g_ush + o; pl = g_usl + o; }
        else                     { size_t o = (size_t)m * DNW + (kc - DNX - DNU);        ph = wbh + o;  pl = wbl + o; }
        cpasync16(sptr(&sm->Ah[buf][r][co]), ph + co);
        cpasync16(sptr(&sm->Al[buf][r][co]), pl + co);
    }
    // B: 64 rows x 64 halves, hi & lo
#pragma unroll
    for (int t = 0; t < 2; ++t) {
        int j = tid + t * NTHR;
        int r = j >> 3, co = (j & 7) * 8;
        size_t o = (size_t)(wn0 + r) * ldw + kc + co;
        cpasync16(sptr(&sm->Bh[buf][r][co]), Wh + o);
        cpasync16(sptr(&sm->Bl[buf][r][co]), Wl + o);
    }
}

// ---------------- 32x64 output tile, 3-stage pipelined K-loop ----------------
// mode 0: tanh -> w buffer (parity s&1)        [P1]
// mode 1: split -> x buffer (parity (s+1)&1)   [P2x]
// mode 2: f32 -> out[b][s][col]                [P2y]
__device__ void tile_run(Smem* sm, float* __restrict__ out,
                         int M0, int N0, int wn0, int Klen, int s,
                         int xpar, int wpar, int mode,
                         const __half* __restrict__ Wh,
                         const __half* __restrict__ Wl, int ldw) {
    const int tid = threadIdx.x;
    const int lane = tid & 31, wid = tid >> 5;
    const int wm = wid & 1, wn = wid >> 1;       // 2(M) x 4(N) warps; warp tile 16x16

    const __half* xh  = g_xh + (size_t)xpar * DB * DNX;
    const __half* xl  = g_xl + (size_t)xpar * DB * DNX;
    const __half* wbh = g_wh + (size_t)wpar * DB * DNW;
    const __half* wbl = g_wl + (size_t)wpar * DB * DNW;

    float acc[8];
#pragma unroll
    for (int i = 0; i < 8; ++i) acc[i] = 0.f;

    const int nch = Klen >> 6;

    load_chunk(sm, 0, M0, wn0, 0,  s, xh, xl, wbh, wbl, Wh, Wl, ldw); cp_commit();
    load_chunk(sm, 1, M0, wn0, 64, s, xh, xl, wbh, wbl, Wh, Wl, ldw); cp_commit();

    const int arow = wm * 16 + (lane & 15);
    const int acol = (lane >> 4) << 3;
    const int brow = wn * 16 + ((lane >> 4) << 3) + (lane & 7);
    const int bcol = ((lane >> 3) & 1) << 3;

    int cur = 0, ld = 2;
    for (int i = 0; i < nch; ++i) {
        if (i == nch - 1) asm volatile("cp.async.wait_group 0;");
        else              asm volatile("cp.async.wait_group 1;");
        __syncthreads();
        if (i + 2 < nch) {
            load_chunk(sm, ld, M0, wn0, (i + 2) << 6, s, xh, xl, wbh, wbl, Wh, Wl, ldw);
            cp_commit();
        }
        const __half* Ah = &sm->Ah[cur][0][0];
        const __half* Al = &sm->Al[cur][0][0];
        const __half* Bh = &sm->Bh[cur][0][0];
        const __half* Bl = &sm->Bl[cur][0][0];
#pragma unroll
        for (int kk = 0; kk < 4; ++kk) {
            unsigned ah[4], al[4], bh[4], bl[4];
            ldsm_x4(ah, sptr(Ah + arow * SSTR + kk * 16 + acol));
            ldsm_x4(al, sptr(Al + arow * SSTR + kk * 16 + acol));
            ldsm_x4(bh, sptr(Bh + brow * SSTR + kk * 16 + bcol));
            ldsm_x4(bl, sptr(Bl + brow * SSTR + kk * 16 + bcol));
            mma16816(acc,     ah, bh);
            mma16816(acc,     al, bh);
            mma16816(acc,     ah, bl);
            mma16816(acc + 4, ah, bh + 2);
            mma16816(acc + 4, al, bh + 2);
            mma16816(acc + 4, ah, bl + 2);
        }
        cur = (cur == 2) ? 0 : cur + 1;
        ld  = (ld  == 2) ? 0 : ld  + 1;
    }

    // ---- epilogue ----
    const int r0 = M0 + wm * 16 + (lane >> 2);
    const int c0 = N0 + wn * 16 + (lane & 3) * 2;

    if (mode == 0) {
        __half* Dh = g_wh + (size_t)(s & 1) * DB * DNW;
        __half* Dl = g_wl + (size_t)(s & 1) * DB * DNW;
#pragma unroll
        for (int nf = 0; nf < 2; ++nf)
#pragma unroll
            for (int rh = 0; rh < 2; ++rh) {
                int row = r0 + rh * 8, col = c0 + nf * 8;
                float v0 = tanhf(acc[nf * 4 + rh * 2 + 0]);
                float v1 = tanhf(acc[nf * 4 + rh * 2 + 1]);
                __half h0, l0, h1, l1; splitf(v0, h0, l0); splitf(v1, h1, l1);
                size_t o = (size_t)row * DNW + col;
                *reinterpret_cast<__half2*>(&Dh[o]) = __halves2half2(h0, h1);
                *reinterpret_cast<__half2*>(&Dl[o]) = __halves2half2(l0, l1);
            }
    } else if (mode == 1) {
        __half* Dh = g_xh + (size_t)((s + 1) & 1) * DB * DNX;
        __half* Dl = g_xl + (size_t)((s + 1) & 1) * DB * DNX;
#pragma unroll
        for (int nf = 0; nf < 2; ++nf)
#pragma unroll
            for (int rh = 0; rh < 2; ++rh) {
                int row = r0 + rh * 8, col = c0 + nf * 8;
                float v0 = acc[nf * 4 + rh * 2 + 0];
                float v1 = acc[nf * 4 + rh * 2 + 1];
                __half h0, l0, h1, l1; splitf(v0, h0, l0); splitf(v1, h1, l1);
                size_t o = (size_t)row * DNX + col;
                *reinterpret_cast<__half2*>(&Dh[o]) = __halves2half2(h0, h1);
                *reinterpret_cast<__half2*>(&Dl[o]) = __halves2half2(l0, l1);
            }
    } else {
#pragma unroll
        for (int nf = 0; nf < 2; ++nf)
#pragma unroll
            for (int rh = 0; rh < 2; ++rh) {
                int row = r0 + rh * 8, col = c0 + nf * 8;
                float2 v = make_float2(acc[nf * 4 + rh * 2 + 0],
                                       acc[nf * 4 + rh * 2 + 1]);
                *reinterpret_cast<float2*>(
                    &out[((size_t)row * DN + s) * DNY + col]) = v;
            }
    }
}

// ---------------- persistent main kernel ----------------
__global__ void __launch_bounds__(NTHR, 1) lure_main(float* __restrict__ out) {
    extern __shared__ __align__(16) char smem_raw[];
    Smem* sm = reinterpret_cast<Smem*>(smem_raw);

    const int bid = blockIdx.x;
    __shared__ unsigned s_base;
    if (threadIdx.x == 0) s_base = atomicAdd(&g_bar_phase, 0u);
    __syncthreads();
    unsigned nbar = 0;

    const int M0 = (bid & 15) * 32;

    for (int k = 0; k <= DN; ++k) {
        // phase alpha: CTAs 0-63: P1(k) (w_k); CTAs 64-127: P2y(k-1) (y_{k-1})
        if (bid < 64) {
            if (k < DN) {
                int N0 = (bid >> 4) * 64;
                tile_run(sm, out, M0, N0, N0, DK1, k, k & 1, 0, 0, g_W1h, g_W1l, DK1);
            }
        } else {
            if (k >= 1) {
                int N0 = ((bid - 64) >> 4) * 64;
                tile_run(sm, out, M0, N0, DNX + N0, DK2, k - 1,
                         (k - 1) & 1, (k - 1) & 1, 2, g_W2h, g_W2l, DK2);
            }
        }
        grid_bar(s_base + (++nbar));
        // phase beta: all 128 CTAs: P2x(k) (x_{k+1})
        if (k < DN) {
            int N0 = (bid >> 4) * 64;
            tile_run(sm, out, M0, N0, N0, DK2, k, k & 1, k & 1, 1, g_W2h, g_W2l, DK2);
            grid_bar(s_base + (++nbar));
        }
    }
}

// ---------------- launch ----------------
extern "C" void kernel_launch(void* const* d_in, const int* in_sizes, int n_in,
                              void* d_out, int out_size) {
    const float* x0  = (const float*)d_in[0];
    const float* us  = (const float*)d_in[1];
    const float* A   = (const float*)d_in[2];
    const float* B1  = (const float*)d_in[3];
    const float* B2  = (const float*)d_in[4];
    const float* C1  = (const float*)d_in[5];
    const float* D11 = (const float*)d_in[6];
    const float* D12 = (const float*)d_in[7];
    const float* C2  = (const float*)d_in[8];
    const float* D21 = (const float*)d_in[9];

    prep_weights<<<512, 256>>>(A, B1, B2, C1, D11, D12, C2, D21, x0);
    prep_us<<<2048, 256>>>(us);

    cudaFuncSetAttribute(lure_main, cudaFuncAttributeMaxDynamicSharedMemorySize,
                         (int)sizeof(Smem));
    lure_main<<<NBLK, NTHR, sizeof(Smem)>>>((float*)d_out);
}

// round 5
// speedup vs baseline: 1.6064x; 1.0570x over previous
#include <cuda_runtime.h>
#include <cuda_fp16.h>
#include <stdint.h>

#define DB    512
#define DN    512
#define DNX   512
#define DNU   256
#define DNY   256
#define DNW   256
#define NBLK  128
#define NTHR  256
#define SSTR  72

// ---------------- device scratch ----------------
__device__ __half g_ush[(size_t)DB * DN * DNU];
__device__ __half g_usl[(size_t)DB * DN * DNU];
__device__ __half g_W1h[DNW * 768];
__device__ __half g_W1l[DNW * 768];
__device__ __half g_W2h[(DNX + DNY) * 1024];
__device__ __half g_W2l[(DNX + DNY) * 1024];
__device__ __half g_xh[2 * DB * DNX];
__device__ __half g_xl[2 * DB * DNX];
__device__ __half g_wh[2 * DB * DNW];
__device__ __half g_wl[2 * DB * DNW];
__device__ unsigned g_bar_count;
__device__ unsigned g_bar_phase;

// ---------------- smem ----------------
struct Smem {
    __half BresH[32 * 1024];        // resident W2x slice (hi), swizzled
    __half BresL[32 * 1024];        // resident W2x slice (lo), swizzled
    __half Ah[3][64][SSTR];
    __half Al[3][64][SSTR];
    __half Bh[3][32][SSTR];
    __half Bl[3][32][SSTR];
};

// ---------------- helpers ----------------
__device__ __forceinline__ void splitf(float v, __half& h, __half& l) {
    h = __float2half_rn(v);
    l = __float2half_rn(v - __half2float(h));
}
__device__ __forceinline__ unsigned sptr(const void* p) {
    return (unsigned)__cvta_generic_to_shared(p);
}
__device__ __forceinline__ void ldsm_x4(unsigned* r, unsigned a) {
    asm volatile("ldmatrix.sync.aligned.m8n8.x4.shared.b16 {%0,%1,%2,%3}, [%4];"
                 : "=r"(r[0]), "=r"(r[1]), "=r"(r[2]), "=r"(r[3]) : "r"(a));
}
__device__ __forceinline__ void mma16816(float* c, const unsigned* a, const unsigned* b) {
    asm volatile(
        "mma.sync.aligned.m16n8k16.row.col.f32.f16.f16.f32 "
        "{%0,%1,%2,%3}, {%4,%5,%6,%7}, {%8,%9}, {%0,%1,%2,%3};\n"
        : "+f"(c[0]), "+f"(c[1]), "+f"(c[2]), "+f"(c[3])
        : "r"(a[0]), "r"(a[1]), "r"(a[2]), "r"(a[3]), "r"(b[0]), "r"(b[1]));
}
__device__ __forceinline__ void cpasync16(unsigned s, const void* g) {
    asm volatile("cp.async.cg.shared.global [%0], [%1], 16;" :: "r"(s), "l"(g));
}
__device__ __forceinline__ void cp_commit() { asm volatile("cp.async.commit_group;"); }

// resident-B swizzle: 16B-chunk column XORed with (row&7) -> ldsm conflict-free
__device__ __forceinline__ int swz(int r, int c16) {
    return r * 1024 + (((c16) ^ (r & 7)) << 3);
}

// grid barrier: 128 CTAs co-resident (<=148 SMs), spin is safe
__device__ __forceinline__ void grid_bar(unsigned target) {
    __threadfence();
    __syncthreads();
    if (threadIdx.x == 0) {
        unsigned a = atomicAdd(&g_bar_count, 1u);
        if (a == NBLK - 1u) {
            g_bar_count = 0u;
            __threadfence();
            atomicExch(&g_bar_phase, target);
        } else {
            unsigned v;
            do { __nanosleep(32); v = *(volatile unsigned*)&g_bar_phase; } while (v != target);
        }
        __threadfence();
    }
    __syncthreads();
}

// ---------------- prep ----------------
__global__ void prep_weights(const float* __restrict__ A,  const float* __restrict__ B1,
                             const float* __restrict__ B2, const float* __restrict__ C1,
                             const float* __restrict__ D11, const float* __restrict__ D12,
                             const float* __restrict__ C2, const float* __restrict__ D21,
                             const float* __restrict__ x0) {
    const int SZ1 = DNW * 768;
    const int SZ2 = (DNX + DNY) * 1024;
    const int SZX = DB * DNX;
    const int tot = SZ1 + SZ2 + SZX;
    for (int i = blockIdx.x * blockDim.x + threadIdx.x; i < tot;
         i += gridDim.x * blockDim.x) {
        float v; __half h, l;
        if (i < SZ1) {
            int n = i / 768, k = i % 768;
            v = (k < DNX) ? C2[n * DNX + k] : D21[n * DNU + (k - DNX)];
            splitf(v, h, l); g_W1h[i] = h; g_W1l[i] = l;
        } else if (i < SZ1 + SZ2) {
            int j = i - SZ1;
            int n = j / 1024, k = j % 1024;
            if (n < DNX) {
                v = (k < DNX) ? A[n * DNX + k]
                  : (k < 768) ? B1[n * DNU + (k - DNX)]
                  : B2[n * DNW + (k - 768)];
            } else {
                int r = n - DNX;
                v = (k < DNX) ? C1[r * DNX + k]
                  : (k < 768) ? D11[r * DNU + (k - DNX)]
                  : D12[r * DNW + (k - 768)];
            }
            splitf(v, h, l); g_W2h[j] = h; g_W2l[j] = l;
        } else {
            int j = i - SZ1 - SZ2;
            v = x0[j];
            splitf(v, h, l); g_xh[j] = h; g_xl[j] = l;
        }
    }
}

__global__ void prep_us(const float* __restrict__ us) {
    size_t n2 = (size_t)DB * DN * DNU / 2;
    const float2* us2 = (const float2*)us;
    __half2* uh2 = (__half2*)g_ush;
    __half2* ul2 = (__half2*)g_usl;
    for (size_t i = blockIdx.x * (size_t)blockDim.x + threadIdx.x; i < n2;
         i += (size_t)gridDim.x * blockDim.x) {
        float2 v = us2[i];
        __half h0, l0, h1, l1; splitf(v.x, h0, l0); splitf(v.y, h1, l1);
        uh2[i] = __halves2half2(h0, h1);
        ul2[i] = __halves2half2(l0, l1);
    }
}

// ---------------- K-chunk maps: order [u | x | w] ----------------
// MODE 0 = P1 (K=768: u,x), 1 = P2x beta (K=1024), 2 = P2y (K=1024)
template<int MODE>
__device__ __forceinline__ int kmap(int i) {
    if (MODE == 0) return (i < 4) ? (DNX + (i << 6)) : ((i - 4) << 6);
    return (i < 4) ? (DNX + (i << 6))
         : (i < 12) ? ((i - 4) << 6)
         : (768 + ((i - 12) << 6));
}

// ---------------- chunk loader ----------------
template<int MODE>
__device__ __forceinline__ void load_chunk(Smem* sm, int buf, int M0, int N0,
                                           int i, int s, int xpar, int wpar) {
    const int tid = threadIdx.x;
    const int kc = kmap<MODE>(i);
    const __half* xh  = g_xh + (size_t)xpar * DB * DNX;
    const __half* xl  = g_xl + (size_t)xpar * DB * DNX;
    const __half* wbh = g_wh + (size_t)wpar * DB * DNW;
    const __half* wbl = g_wl + (size_t)wpar * DB * DNW;
    // A: 64 rows x 64 halves (hi & lo)
#pragma unroll
    for (int t = 0; t < 2; ++t) {
        int j = tid + t * NTHR;
        int r = j >> 3, co = (j & 7) * 8;
        int m = M0 + r;
        const __half *ph, *pl;
        if (kc < DNX)      { size_t o = (size_t)m * DNX + kc;                    ph = xh + o;    pl = xl + o; }
        else if (kc < 768) { size_t o = ((size_t)m * DN + s) * DNU + (kc - DNX); ph = g_ush + o; pl = g_usl + o; }
        else               { size_t o = (size_t)m * DNW + (kc - 768);            ph = wbh + o;   pl = wbl + o; }
        cpasync16(sptr(&sm->Ah[buf][r][co]), ph + co);
        cpasync16(sptr(&sm->Al[buf][r][co]), pl + co);
    }
    // B: 32 rows (streamed modes only)
    if (MODE != 1) {
        int r = tid >> 3, co = (tid & 7) * 8;
        const __half* Wh = (MODE == 0) ? g_W1h : g_W2h;
        const __half* Wl = (MODE == 0) ? g_W1l : g_W2l;
        int ldw  = (MODE == 0) ? 768 : 1024;
        int row  = ((MODE == 2) ? (DNX + N0) : N0) + r;
        size_t o = (size_t)row * ldw + kc + co;
        cpasync16(sptr(&sm->Bh[buf][r][co]), Wh + o);
        cpasync16(sptr(&sm->Bl[buf][r][co]), Wl + o);
    }
    cp_commit();
}

// prefetch chunks 0,1 (u columns: always ready) into bufs 0,1
template<int MODE>
__device__ __forceinline__ void prefetch2(Smem* sm, int M0, int N0, int s) {
    load_chunk<MODE>(sm, 0, M0, N0, 0, s, 0, 0);
    load_chunk<MODE>(sm, 1, M0, N0, 1, s, 0, 0);
}

// ---------------- 64x32 tile, 3-stage pipelined K-loop ----------------
template<int MODE>
__device__ void tile_run(Smem* sm, float* __restrict__ out,
                         int M0, int N0, int s, int xpar, int wpar) {
    const int tid = threadIdx.x;
    const int lane = tid & 31, wid = tid >> 5;
    const int wm = wid & 3, wn = wid >> 2;      // 4(M) x 2(N) warps, 16x16 tile

    float acc[8];
#pragma unroll
    for (int i = 0; i < 8; ++i) acc[i] = 0.f;

    const int nch = (MODE == 0) ? 12 : 16;

    const int arow = wm * 16 + (lane & 15);
    const int acol = (lane >> 4) << 3;
    const int brow = wn * 16 + ((lane >> 4) << 3) + (lane & 7);
    const int bc16 = (lane >> 3) & 1;           // 16B-chunk within kstep

    int cur = 0, ld = 2;
    for (int i = 0; i < nch; ++i) {
        if (i == nch - 1) asm volatile("cp.async.wait_group 0;");
        else              asm volatile("cp.async.wait_group 1;");
        __syncthreads();
        if (i + 2 < nch)
            load_chunk<MODE>(sm, ld, M0, N0, i + 2, s, xpar, wpar);
        const __half* Ah = &sm->Ah[cur][0][0];
        const __half* Al = &sm->Al[cur][0][0];
        const int kbase16 = kmap<MODE>(i) >> 3;   // chunk's 16B-column base in resident W2
#pragma unroll
        for (int kk = 0; kk < 4; ++kk) {
            unsigned ah[4], al[4], bh[4], bl[4];
            ldsm_x4(ah, sptr(Ah + arow * SSTR + kk * 16 + acol));
            ldsm_x4(al, sptr(Al + arow * SSTR + kk * 16 + acol));
            if (MODE == 1) {
                int c16 = kbase16 + kk * 2 + bc16;   // FIX: include chunk K-offset
                ldsm_x4(bh, sptr(&sm->BresH[swz(brow, c16)]));
                ldsm_x4(bl, sptr(&sm->BresL[swz(brow, c16)]));
            } else {
                const __half* Bh = &sm->Bh[cur][0][0];
                const __half* Bl = &sm->Bl[cur][0][0];
                ldsm_x4(bh, sptr(Bh + brow * SSTR + kk * 16 + (bc16 << 3)));
                ldsm_x4(bl, sptr(Bl + brow * SSTR + kk * 16 + (bc16 << 3)));
            }
            mma16816(acc,     ah, bh);
            mma16816(acc,     al, bh);
            mma16816(acc,     ah, bl);
            mma16816(acc + 4, ah, bh + 2);
            mma16816(acc + 4, al, bh + 2);
            mma16816(acc + 4, ah, bl + 2);
        }
        cur = (cur == 2) ? 0 : cur + 1;
        ld  = (ld  == 2) ? 0 : ld  + 1;
    }

    // ---- epilogue ----
    const int r0 = M0 + wm * 16 + (lane >> 2);
    const int c0 = N0 + wn * 16 + (lane & 3) * 2;

    if (MODE == 0) {                        // w_s = tanh(.)
        __half* Dh = g_wh + (size_t)(s & 1) * DB * DNW;
        __half* Dl = g_wl + (size_t)(s & 1) * DB * DNW;
#pragma unroll
        for (int nf = 0; nf < 2; ++nf)
#pragma unroll
            for (int rh = 0; rh < 2; ++rh) {
                int row = r0 + rh * 8, col = c0 + nf * 8;
                float v0 = tanhf(acc[nf * 4 + rh * 2 + 0]);
                float v1 = tanhf(acc[nf * 4 + rh * 2 + 1]);
                __half h0, l0, h1, l1; splitf(v0, h0, l0); splitf(v1, h1, l1);
                size_t o = (size_t)row * DNW + col;
                *reinterpret_cast<__half2*>(&Dh[o]) = __halves2half2(h0, h1);
                *reinterpret_cast<__half2*>(&Dl[o]) = __halves2half2(l0, l1);
            }
    } else if (MODE == 1) {                 // x_{s+1}
        __half* Dh = g_xh + (size_t)((s + 1) & 1) * DB * DNX;
        __half* Dl = g_xl + (size_t)((s + 1) & 1) * DB * DNX;
#pragma unroll
        for (int nf = 0; nf < 2; ++nf)
#pragma unroll
            for (int rh = 0; rh < 2; ++rh) {
                int row = r0 + rh * 8, col = c0 + nf * 8;
                float v0 = acc[nf * 4 + rh * 2 + 0];
                float v1 = acc[nf * 4 + rh * 2 + 1];
                __half h0, l0, h1, l1; splitf(v0, h0, l0); splitf(v1, h1, l1);
                size_t o = (size_t)row * DNX + col;
                *reinterpret_cast<__half2*>(&Dh[o]) = __halves2half2(h0, h1);
                *reinterpret_cast<__half2*>(&Dl[o]) = __halves2half2(l0, l1);
            }
    } else {                                // y_s
#pragma unroll
        for (int nf = 0; nf < 2; ++nf)
#pragma unroll
            for (int rh = 0; rh < 2; ++rh) {
                int row = r0 + rh * 8, col = c0 + nf * 8;
                float2 v = make_float2(acc[nf * 4 + rh * 2 + 0],
                                       acc[nf * 4 + rh * 2 + 1]);
                *reinterpret_cast<float2*>(
                    &out[((size_t)row * DN + s) * DNY + col]) = v;
            }
    }
}

// ---------------- persistent main kernel ----------------
__global__ void __launch_bounds__(NTHR, 1) lure_main(float* __restrict__ out) {
    extern __shared__ __align__(16) char smem_raw[];
    Smem* sm = reinterpret_cast<Smem*>(smem_raw);

    const int bid = blockIdx.x;
    const int tid = threadIdx.x;
    const int Mg = bid & 7, Ng = bid >> 3;
    const int M0 = Mg * 64;
    const int N0b = Ng * 32;                    // beta N slice (W2 x-rows)
    const int N0a = (Ng < 8) ? Ng * 32 : (Ng - 8) * 32;  // alpha N slice

    // resident W2x slice: 32 rows x 1024 halves, hi & lo, swizzled
    for (int idx = tid; idx < 32 * 128; idx += NTHR) {
        int r = idx >> 7, c16 = idx & 127;
        int d = swz(r, c16);
        cpasync16(sptr(&sm->BresH[d]), g_W2h + (size_t)(N0b + r) * 1024 + c16 * 8);
        cpasync16(sptr(&sm->BresL[d]), g_W2l + (size_t)(N0b + r) * 1024 + c16 * 8);
    }
    cp_commit();
    asm volatile("cp.async.wait_group 0;");
    __syncthreads();

    __shared__ unsigned s_base;
    if (tid == 0) s_base = atomicAdd(&g_bar_phase, 0u);
    __syncthreads();
    unsigned nbar = 0;

    if (Ng < 8) prefetch2<0>(sm, M0, N0a, 0);   // P1(0) u-chunks

    for (int k = 0; k <= DN; ++k) {
        // ---- phase alpha: Ng<8 -> P1(k); Ng>=8 -> P2y(k-1) ----
        if (Ng < 8) {
            if (k < DN) tile_run<0>(sm, out, M0, N0a, k, k & 1, 0);
        } else {
            if (k >= 1) tile_run<2>(sm, out, M0, N0a, k - 1, (k - 1) & 1, (k - 1) & 1);
        }
        if (k < DN) { __syncthreads(); prefetch2<1>(sm, M0, N0b, k); }
        grid_bar(s_base + (++nbar));

        // ---- phase beta: all CTAs -> P2x(k) ----
        if (k < DN) {
            tile_run<1>(sm, out, M0, N0b, k, k & 1, k & 1);
            __syncthreads();
            if (Ng < 8) { if (k + 1 < DN) prefetch2<0>(sm, M0, N0a, k + 1); }
            else        { prefetch2<2>(sm, M0, N0a, k); }
            grid_bar(s_base + (++nbar));
        }
    }
}

// ---------------- launch ----------------
extern "C" void kernel_launch(void* const* d_in, const int* in_sizes, int n_in,
                              void* d_out, int out_size) {
    const float* x0  = (const float*)d_in[0];
    const float* us  = (const float*)d_in[1];
    const float* A   = (const float*)d_in[2];
    const float* B1  = (const float*)d_in[3];
    const float* B2  = (const float*)d_in[4];
    const float* C1  = (const float*)d_in[5];
    const float* D11 = (const float*)d_in[6];
    const float* D12 = (const float*)d_in[7];
    const float* C2  = (const float*)d_in[8];
    const float* D21 = (const float*)d_in[9];

    prep_weights<<<512, 256>>>(A, B1, B2, C1, D11, D12, C2, D21, x0);
    prep_us<<<2048, 256>>>(us);

    cudaFuncSetAttribute(lure_main, cudaFuncAttributeMaxDynamicSharedMemorySize,
                         (int)sizeof(Smem));
    lure_main<<<NBLK, NTHR, sizeof(Smem)>>>((float*)d_out);
}